// round 7
// baseline (speedup 1.0000x reference)
#include <cuda_runtime.h>
#include <cstdint>

#define NN 50000
#define EE 800000
#define IND 16
#define H 64
#define EAD 8

#define GRID_P 148

// Scratch state (no cudaMalloc allowed)
__device__ float g_h[NN * H];        // fp32 h (nodehead input)
__device__ float g_agg[NN * H];      // aggregation buffer
__device__ uint32_t g_hh2[NN * 32];  // h packed bf16x2 hi, pair-interleaved {kp,kp+4}
__device__ uint32_t g_hl2[NN * 32];  // lo
__device__ uint32_t g_eah2[EE * 8];  // ea packed hi: per edge 4 uint2 slots {pair,0}
__device__ uint32_t g_eal2[EE * 8];

// Weights, pair-format: row r = s*4+j holds uint2 {Wpair(8s+j,n), Wpair(8s+j+4,n)}
// stored as u32 [row*RS + 2n(+1)]
__device__ uint32_t g_Wm_h[36 * 136], g_Wm_l[36 * 136];   // msg  K=136 N=64  RS=136
__device__ uint32_t g_Wu_h[32 * 136], g_Wu_l[32 * 136];   // upd  K=128 N=64  RS=136
__device__ uint32_t g_W1_h[36 * 264], g_W1_l[36 * 264];   // ed1  K=136 N=128 RS=264
__device__ uint32_t g_W2_h[32 * 136], g_W2_l[32 * 136];   // ed2  K=128 N=64  RS=136

// ---------------------------------------------------------------------------
__device__ __forceinline__ void splitpack(float a0, float a1, uint32_t& hi, uint32_t& lo) {
    uint32_t h, l;
    asm("cvt.rn.bf16x2.f32 %0, %1, %2;" : "=r"(h) : "f"(a1), "f"(a0));
    float r0 = a0 - __uint_as_float(h << 16);
    float r1 = a1 - __uint_as_float(h & 0xFFFF0000u);
    asm("cvt.rn.bf16x2.f32 %0, %1, %2;" : "=r"(l) : "f"(r1), "f"(r0));
    hi = h; lo = l;
}

__device__ __forceinline__ void mma_bf16(float* c, const uint32_t* a, uint32_t b0, uint32_t b1) {
    asm volatile(
        "mma.sync.aligned.m16n8k16.row.col.f32.bf16.bf16.f32 "
        "{%0,%1,%2,%3}, {%4,%5,%6,%7}, {%8,%9}, {%0,%1,%2,%3};"
        : "+f"(c[0]), "+f"(c[1]), "+f"(c[2]), "+f"(c[3])
        : "r"(a[0]), "r"(a[1]), "r"(a[2]), "r"(a[3]), "r"(b0), "r"(b1));
}

#define CP_ASYNC16(saddr, gptr) \
    asm volatile("cp.async.cg.shared.global [%0], [%1], 16;" :: "r"(saddr), "l"(gptr) : "memory")
#define CP_COMMIT() asm volatile("cp.async.commit_group;" ::: "memory")
#define CP_WAIT1()  asm volatile("cp.async.wait_group 1;" ::: "memory")

// index of pair p (0..31) in the pair-interleaved packed-h u32 layout
__device__ __forceinline__ int hpack_idx(int p) {
    int s = p >> 3, r = p & 7;
    return (r < 4) ? (s * 4 + r) * 2 : (s * 4 + r - 4) * 2 + 1;
}

// ---------------------------------------------------------------------------
// Setup: split weights into pair-format
// ---------------------------------------------------------------------------
__device__ __forceinline__ void emit_w(const float* W, int Kp, int N, int RS,
                                       uint32_t* oh, uint32_t* ol, int i) {
    int row = i / N, n = i - row * N;
    int s = row >> 2, j = row & 3;
    int kp1 = 8 * s + j, kp2 = kp1 + 4;
    float a0 = 0.f, a1 = 0.f, c0 = 0.f, c1 = 0.f;
    if (kp1 < Kp) { a0 = W[(2 * kp1) * N + n]; a1 = W[(2 * kp1 + 1) * N + n]; }
    if (kp2 < Kp) { c0 = W[(2 * kp2) * N + n]; c1 = W[(2 * kp2 + 1) * N + n]; }
    uint32_t h1, l1, h2, l2;
    splitpack(a0, a1, h1, l1);
    splitpack(c0, c1, h2, l2);
    oh[row * RS + 2 * n] = h1; oh[row * RS + 2 * n + 1] = h2;
    ol[row * RS + 2 * n] = l1; ol[row * RS + 2 * n + 1] = l2;
}

#define SW_M (36*64)
#define SW_U (32*64)
#define SW_1 (36*128)
#define SW_2 (32*64)
#define SW_TOTAL (SW_M + SW_U + SW_1 + SW_2)

__global__ void split_w_kernel(const float* __restrict__ Wm, const float* __restrict__ Wu,
                               const float* __restrict__ W1, const float* __restrict__ W2) {
    int i = blockIdx.x * 256 + threadIdx.x;
    if (i < SW_M) { emit_w(Wm, 68, 64, 136, g_Wm_h, g_Wm_l, i); return; }
    i -= SW_M;
    if (i < SW_U) { emit_w(Wu, 64, 64, 136, g_Wu_h, g_Wu_l, i); return; }
    i -= SW_U;
    if (i < SW_1) { emit_w(W1, 68, 128, 264, g_W1_h, g_W1_l, i); return; }
    i -= SW_1;
    if (i < SW_2) { emit_w(W2, 64, 64, 136, g_W2_h, g_W2_l, i); return; }
}

// prep: split edge_attr into pair-format (+zero slot) AND zero g_agg
__global__ void prep_kernel(const float* __restrict__ ea) {
    int i = blockIdx.x * 256 + threadIdx.x;
    if (i < NN * H) g_agg[i] = 0.f;
    if (i < EE * 4) {
        int e = i >> 2, j = i & 3;
        float2 v = *(const float2*)(ea + e * EAD + 2 * j);
        uint32_t h, l;
        splitpack(v.x, v.y, h, l);
        g_eah2[e * 8 + 2 * j] = h; g_eah2[e * 8 + 2 * j + 1] = 0;
        g_eal2[e * 8 + 2 * j] = l; g_eal2[e * 8 + 2 * j + 1] = 0;
    }
}

// ---------------------------------------------------------------------------
// Encoder: h = x @ W_enc + b_enc ; writes fp32 + packed pair-interleaved
// ---------------------------------------------------------------------------
__global__ void enc_kernel(const float* __restrict__ x,
                           const float* __restrict__ W,
                           const float* __restrict__ b) {
    __shared__ float Ws[IND * H];
    __shared__ float bs[H];
    for (int i = threadIdx.x; i < IND * H; i += blockDim.x) Ws[i] = W[i];
    if (threadIdx.x < H) bs[threadIdx.x] = b[threadIdx.x];
    __syncthreads();
    int node = blockIdx.x * blockDim.x + threadIdx.x;
    if (node >= NN) return;
    float xv[IND];
#pragma unroll
    for (int k = 0; k < IND; k++) xv[k] = x[node * IND + k];
#pragma unroll 4
    for (int n = 0; n < H; n += 2) {
        float a0 = bs[n], a1 = bs[n + 1];
#pragma unroll
        for (int k = 0; k < IND; k++) {
            a0 += xv[k] * Ws[k * H + n];
            a1 += xv[k] * Ws[k * H + n + 1];
        }
        g_h[node * H + n] = a0;
        g_h[node * H + n + 1] = a1;
        uint32_t h, l;
        splitpack(a0, a1, h, l);
        int idx = hpack_idx(n >> 1);
        g_hh2[node * 32 + idx] = h;
        g_hl2[node * 32 + idx] = l;
    }
}

// ---------------------------------------------------------------------------
// Shared staging for msg/edgehead: tile = 64 edges, row = 36 uint2
//   slots 0..15 src-h, 16..31 dst-h, 32..35 ea(+zero pad)
// ---------------------------------------------------------------------------
#define ASLOT 36
#define ABUF (64 * ASLOT)      // uint2 per (hi or lo) half-buffer

__device__ __forceinline__ void stage_tile(uint2* buf,
        const int* __restrict__ src, const int* __restrict__ dst,
        int tbase, int tid) {
    int e = tid >> 2, sub = tid & 3;
    int ge = tbase + e;
    int lo = sub >> 1;
    uint2* row = buf + lo * ABUF + e * ASLOT;
    uint32_t rb = (uint32_t)__cvta_generic_to_shared(row);
    const uint32_t* gh = lo ? g_hl2 : g_hh2;
    if ((sub & 1) == 0) {
        const uint32_t* p = gh + src[ge] * 32;
#pragma unroll
        for (int j = 0; j < 8; j++) CP_ASYNC16(rb + j * 16, p + j * 4);
        const uint32_t* pe = (lo ? g_eal2 : g_eah2) + ge * 8;
        CP_ASYNC16(rb + 256, pe);
        CP_ASYNC16(rb + 272, pe + 4);
    } else {
        const uint32_t* p = gh + dst[ge] * 32;
#pragma unroll
        for (int j = 0; j < 8; j++) CP_ASYNC16(rb + 128 + j * 16, p + j * 4);
    }
}

// ---------------------------------------------------------------------------
// Message + scatter-add: persistent, double-buffered, B in REGISTERS.
// Tile 64 edges x 64 n. 8 warps = 4M x 2N, warp 16x32.
// ---------------------------------------------------------------------------
#define NT_MSG (EE / 64)
#define MSG_SMEM (4 * ABUF * 8)     // 73728 B

__global__ void __launch_bounds__(256, 1)
msg_kernel(const int* __restrict__ ei, const float* __restrict__ bias) {
    extern __shared__ uint2 smU[];
    const int* src = ei;
    const int* dst = ei + EE;
    const int tid = threadIdx.x;
    const int lane = tid & 31, warp = tid >> 5;
    const int g = lane >> 2, tig = lane & 3;
    const int warpM = warp & 3, warpN = warp >> 2;
    const int row0 = warpM * 16 + g;

    // weight panel in registers (loaded once per persistent block)
    uint2 brh[9][4], brl[9][4];
    const uint2* WmH = (const uint2*)g_Wm_h;
    const uint2* WmL = (const uint2*)g_Wm_l;
#pragma unroll
    for (int s = 0; s < 9; s++)
#pragma unroll
        for (int nt = 0; nt < 4; nt++) {
            int idx = (s * 4 + tig) * 68 + warpN * 32 + nt * 8 + g;
            brh[s][nt] = WmH[idx];
            brl[s][nt] = WmL[idx];
        }
    float2 bv[4];
#pragma unroll
    for (int nt = 0; nt < 4; nt++) {
        int n = warpN * 32 + nt * 8 + 2 * tig;
        bv[nt] = make_float2(__ldg(bias + n), __ldg(bias + n + 1));
    }

    int t = blockIdx.x, cur = 0;
    if (t < NT_MSG) stage_tile(smU, src, dst, t * 64, tid);
    CP_COMMIT();

    for (; t < NT_MSG; t += GRID_P) {
        int tn = t + GRID_P;
        if (tn < NT_MSG) stage_tile(smU + (cur ^ 1) * 2 * ABUF, src, dst, tn * 64, tid);
        CP_COMMIT();
        CP_WAIT1();
        __syncthreads();

        const uint2* Ah = smU + cur * 2 * ABUF;
        const uint2* Al = Ah + ABUF;
        float acc[4][4] = {};
#pragma unroll
        for (int s = 0; s < 9; s++) {
            uint2 u0h = Ah[ row0      * ASLOT + s * 4 + tig];
            uint2 u1h = Ah[(row0 + 8) * ASLOT + s * 4 + tig];
            uint2 u0l = Al[ row0      * ASLOT + s * 4 + tig];
            uint2 u1l = Al[(row0 + 8) * ASLOT + s * 4 + tig];
            uint32_t ah[4] = {u0h.x, u1h.x, u0h.y, u1h.y};
            uint32_t al[4] = {u0l.x, u1l.x, u0l.y, u1l.y};
#pragma unroll
            for (int nt = 0; nt < 4; nt++) {
                mma_bf16(acc[nt], ah, brh[s][nt].x, brh[s][nt].y);
                mma_bf16(acc[nt], al, brh[s][nt].x, brh[s][nt].y);
                mma_bf16(acc[nt], ah, brl[s][nt].x, brl[s][nt].y);
            }
        }

        const int tbase = t * 64;
        const int d0 = dst[tbase + row0];
        const int d1 = dst[tbase + row0 + 8];
#pragma unroll
        for (int nt = 0; nt < 4; nt++) {
            int n = warpN * 32 + nt * 8 + 2 * tig;
            atomicAdd((float2*)(g_agg + d0 * H + n),
                      make_float2(fmaxf(acc[nt][0] + bv[nt].x, 0.f),
                                  fmaxf(acc[nt][1] + bv[nt].y, 0.f)));
            atomicAdd((float2*)(g_agg + d1 * H + n),
                      make_float2(fmaxf(acc[nt][2] + bv[nt].x, 0.f),
                                  fmaxf(acc[nt][3] + bv[nt].y, 0.f)));
        }
        __syncthreads();
        cur ^= 1;
    }
}

// ---------------------------------------------------------------------------
// Update: h = relu([h | agg] @ W_upd + b), zeroes g_agg as it reads it.
// Tile 64 nodes, 4M x 2N, B in registers.
// ---------------------------------------------------------------------------
#define UPD_SMEM (2 * 64 * ASLOT * 8)   // 36864 B

__global__ void __launch_bounds__(256, 1)
upd_kernel(const float* __restrict__ bias) {
    extern __shared__ uint2 smU[];
    uint2* Ah = smU;
    uint2* Al = smU + 64 * ASLOT;
    const int nbase = blockIdx.x * 64;
    const int tid = threadIdx.x;
    const int lane = tid & 31, warp = tid >> 5;
    const int g = lane >> 2, tig = lane & 3;
    const int warpM = warp & 3, warpN = warp >> 2;
    const int row0 = warpM * 16 + g;

    uint2 brh[8][4], brl[8][4];
    const uint2* WuH = (const uint2*)g_Wu_h;
    const uint2* WuL = (const uint2*)g_Wu_l;
#pragma unroll
    for (int s = 0; s < 8; s++)
#pragma unroll
        for (int nt = 0; nt < 4; nt++) {
            int idx = (s * 4 + tig) * 68 + warpN * 32 + nt * 8 + g;
            brh[s][nt] = WuH[idx];
            brl[s][nt] = WuL[idx];
        }

    // stage: slots 0..15 = packed h (copy), 16..31 = agg pairs (split + zero)
    for (int i = tid; i < 64 * 32; i += 256) {
        int nd = i >> 5, u = i & 31;
        int gn = nbase + nd;
        if (u < 16) {
            uint2 h = make_uint2(0, 0), l = make_uint2(0, 0);
            if (gn < NN) {
                h = ((const uint2*)g_hh2)[gn * 16 + u];
                l = ((const uint2*)g_hl2)[gn * 16 + u];
            }
            Ah[nd * ASLOT + u] = h;
            Al[nd * ASLOT + u] = l;
        } else {
            int s = u >> 2, j = u & 3;          // s in 4..7
            int pa1 = 8 * (s - 4) + j, pa2 = pa1 + 4;
            uint32_t h1 = 0, l1 = 0, h2 = 0, l2 = 0;
            if (gn < NN) {
                float2 v1 = *(float2*)(g_agg + gn * H + 2 * pa1);
                float2 v2 = *(float2*)(g_agg + gn * H + 2 * pa2);
                splitpack(v1.x, v1.y, h1, l1);
                splitpack(v2.x, v2.y, h2, l2);
                *(float2*)(g_agg + gn * H + 2 * pa1) = make_float2(0.f, 0.f);
                *(float2*)(g_agg + gn * H + 2 * pa2) = make_float2(0.f, 0.f);
            }
            Ah[nd * ASLOT + u] = make_uint2(h1, h2);
            Al[nd * ASLOT + u] = make_uint2(l1, l2);
        }
    }
    __syncthreads();

    float acc[4][4] = {};
#pragma unroll
    for (int s = 0; s < 8; s++) {
        uint2 u0h = Ah[ row0      * ASLOT + s * 4 + tig];
        uint2 u1h = Ah[(row0 + 8) * ASLOT + s * 4 + tig];
        uint2 u0l = Al[ row0      * ASLOT + s * 4 + tig];
        uint2 u1l = Al[(row0 + 8) * ASLOT + s * 4 + tig];
        uint32_t ah[4] = {u0h.x, u1h.x, u0h.y, u1h.y};
        uint32_t al[4] = {u0l.x, u1l.x, u0l.y, u1l.y};
#pragma unroll
        for (int nt = 0; nt < 4; nt++) {
            mma_bf16(acc[nt], ah, brh[s][nt].x, brh[s][nt].y);
            mma_bf16(acc[nt], al, brh[s][nt].x, brh[s][nt].y);
            mma_bf16(acc[nt], ah, brl[s][nt].x, brl[s][nt].y);
        }
    }

    const int gn0 = nbase + row0, gn1 = nbase + row0 + 8;
#pragma unroll
    for (int nt = 0; nt < 4; nt++) {
        int n = warpN * 32 + nt * 8 + 2 * tig;
        int p = n >> 1;
        int idx = hpack_idx(p);
        float bb0 = __ldg(bias + n), bb1 = __ldg(bias + n + 1);
        if (gn0 < NN) {
            float v0 = fmaxf(acc[nt][0] + bb0, 0.f);
            float v1 = fmaxf(acc[nt][1] + bb1, 0.f);
            *(float2*)(g_h + gn0 * H + n) = make_float2(v0, v1);
            splitpack(v0, v1, g_hh2[gn0 * 32 + idx], g_hl2[gn0 * 32 + idx]);
        }
        if (gn1 < NN) {
            float v0 = fmaxf(acc[nt][2] + bb0, 0.f);
            float v1 = fmaxf(acc[nt][3] + bb1, 0.f);
            *(float2*)(g_h + gn1 * H + n) = make_float2(v0, v1);
            splitpack(v0, v1, g_hh2[gn1 * 32 + idx], g_hl2[gn1 * 32 + idx]);
        }
    }
}

// ---------------------------------------------------------------------------
// Node head (FFMA): out = relu(h @ W1 + b1) @ W2 + b2
// ---------------------------------------------------------------------------
__global__ void __launch_bounds__(256)
nodehead_kernel(const float* __restrict__ W1, const float* __restrict__ b1,
                const float* __restrict__ W2, const float* __restrict__ b2,
                float* __restrict__ out) {
    __shared__ float As[64 * 64];
    __shared__ float Ws[64 * 64];
    __shared__ float W2s[64 * 2];
    __shared__ float b2s[2];
    int nbase = blockIdx.x * 64;

    for (int i = threadIdx.x; i < 64 * 64; i += 256) Ws[i] = W1[i];
    if (threadIdx.x < 128) W2s[threadIdx.x] = W2[threadIdx.x];
    if (threadIdx.x < 2) b2s[threadIdx.x] = b2[threadIdx.x];
    for (int i = threadIdx.x; i < 64 * 64; i += 256) {
        int nd = i >> 6, k = i & 63;
        int gn = nbase + nd;
        As[i] = (gn < NN) ? g_h[gn * H + k] : 0.f;
    }
    __syncthreads();

    int tn = threadIdx.x & 15, te = threadIdx.x >> 4;
    float acc[4][4] = {};
    for (int k = 0; k < 64; k += 4) {
        float4 av4[4];
#pragma unroll
        for (int i = 0; i < 4; i++)
            av4[i] = *(const float4*)(As + (te * 4 + i) * 64 + k);
        const float* av = (const float*)av4;
#pragma unroll
        for (int kk = 0; kk < 4; kk++) {
            float4 w = *(const float4*)(Ws + (k + kk) * H + tn * 4);
#pragma unroll
            for (int i = 0; i < 4; i++) {
                float a = av[i * 4 + kk];
                acc[i][0] += a * w.x;
                acc[i][1] += a * w.y;
                acc[i][2] += a * w.z;
                acc[i][3] += a * w.w;
            }
        }
    }
    __syncthreads();

    float4 bvv = *(const float4*)(b1 + tn * 4);
    const float* bvp = (const float*)&bvv;
#pragma unroll
    for (int i = 0; i < 4; i++)
#pragma unroll
        for (int j = 0; j < 4; j++)
            As[(tn * 4 + j) * 64 + te * 4 + i] = fmaxf(acc[i][j] + bvp[j], 0.f);
    __syncthreads();

    if (threadIdx.x < 128) {
        int nd = threadIdx.x & 63, j = threadIdx.x >> 6;
        int gn = nbase + nd;
        if (gn < NN) {
            float s = b2s[j];
#pragma unroll 8
            for (int k = 0; k < 64; k++) s += As[k * 64 + nd] * W2s[k * 2 + j];
            out[gn * 2 + j] = s;
        }
    }
}

// ---------------------------------------------------------------------------
// Edge head: persistent, weights resident (pair-format), double-buffered.
// 136 -> 128 -> 64 -> 6, tile 64 edges. 8 warps = 4M x 2N.
// ---------------------------------------------------------------------------
#define NT_EH (EE / 64)
#define EH_SMEM (4*ABUF*8 + 2*9504*4 + 2*4352*4 + 390*4)   // 186136 B

__global__ void __launch_bounds__(256, 1)
edgehead_kernel(const int* __restrict__ ei,
                const float* __restrict__ b1, const float* __restrict__ b2,
                const float* __restrict__ W3, const float* __restrict__ b3,
                float* __restrict__ out) {
    extern __shared__ uint2 smU[];
    uint32_t* W1h = (uint32_t*)(smU + 4 * ABUF);   // 9504 u32
    uint32_t* W1l = W1h + 9504;
    uint32_t* W2h = W1l + 9504;                    // 4352
    uint32_t* W2l = W2h + 4352;
    float*    W3s = (float*)(W2l + 4352);          // 384
    float*    b3s = W3s + 384;                     // 6
    const int* src = ei;
    const int* dst = ei + EE;
    const int tid = threadIdx.x;

    for (int i = tid; i < 9504; i += 256) { W1h[i] = g_W1_h[i]; W1l[i] = g_W1_l[i]; }
    for (int i = tid; i < 4352; i += 256) { W2h[i] = g_W2_h[i]; W2l[i] = g_W2_l[i]; }
    for (int i = tid; i < 384; i += 256) W3s[i] = W3[i];
    if (tid < 6) b3s[tid] = b3[tid];

    const int lane = tid & 31, warp = tid >> 5;
    const int g = lane >> 2, tig = lane & 3;
    const int warpM = warp & 3, warpN = warp >> 2;
    const int row0 = warpM * 16 + g;
    __syncthreads();

    const uint2* W1hU = (const uint2*)W1h;
    const uint2* W1lU = (const uint2*)W1l;
    const uint2* W2hU = (const uint2*)W2h;
    const uint2* W2lU = (const uint2*)W2l;

    int t = blockIdx.x, cur = 0;
    if (t < NT_EH) stage_tile(smU, src, dst, t * 64, tid);
    CP_COMMIT();

    for (; t < NT_EH; t += GRID_P) {
        int tn = t + GRID_P;
        if (tn < NT_EH) stage_tile(smU + (cur ^ 1) * 2 * ABUF, src, dst, tn * 64, tid);
        CP_COMMIT();
        CP_WAIT1();
        __syncthreads();

        uint2* Ah = smU + cur * 2 * ABUF;
        uint2* Al = Ah + ABUF;
        const int ebase = t * 64;

        // GEMM1: [64,136] @ [136,128] ; warp 16 x 64 (8 n-tiles)
        float acc1[8][4] = {};
#pragma unroll
        for (int s = 0; s < 9; s++) {
            uint2 u0h = Ah[ row0      * ASLOT + s * 4 + tig];
            uint2 u1h = Ah[(row0 + 8) * ASLOT + s * 4 + tig];
            uint2 u0l = Al[ row0      * ASLOT + s * 4 + tig];
            uint2 u1l = Al[(row0 + 8) * ASLOT + s * 4 + tig];
            uint32_t ah[4] = {u0h.x, u1h.x, u0h.y, u1h.y};
            uint32_t al[4] = {u0l.x, u1l.x, u0l.y, u1l.y};
#pragma unroll
            for (int nt = 0; nt < 8; nt++) {
                int bidx = (s * 4 + tig) * 132 + warpN * 64 + nt * 8 + g;
                uint2 bh = W1hU[bidx];
                uint2 bl = W1lU[bidx];
                mma_bf16(acc1[nt], ah, bh.x, bh.y);
                mma_bf16(acc1[nt], al, bh.x, bh.y);
                mma_bf16(acc1[nt], ah, bl.x, bl.y);
            }
        }
        __syncthreads();   // all F reads done

        // epilogue1: C1 = splitpack(relu(acc1+b1)) -> pair-interleaved in Ah/Al
#pragma unroll
        for (int nt = 0; nt < 8; nt += 2) {
            int n0 = warpN * 64 + nt * 8 + 2 * tig;
            int n1 = n0 + 8;
            float b00 = __ldg(b1 + n0), b01 = __ldg(b1 + n0 + 1);
            float b10 = __ldg(b1 + n1), b11 = __ldg(b1 + n1 + 1);
            int u = (warpN * 4 + (nt >> 1)) * 4 + tig;
            uint32_t hA, lA, hB, lB;
            splitpack(fmaxf(acc1[nt][0] + b00, 0.f), fmaxf(acc1[nt][1] + b01, 0.f), hA, lA);
            splitpack(fmaxf(acc1[nt + 1][0] + b10, 0.f), fmaxf(acc1[nt + 1][1] + b11, 0.f), hB, lB);
            Ah[row0 * ASLOT + u] = make_uint2(hA, hB);
            Al[row0 * ASLOT + u] = make_uint2(lA, lB);
            splitpack(fmaxf(acc1[nt][2] + b00, 0.f), fmaxf(acc1[nt][3] + b01, 0.f), hA, lA);
            splitpack(fmaxf(acc1[nt + 1][2] + b10, 0.f), fmaxf(acc1[nt + 1][3] + b11, 0.f), hB, lB);
            Ah[(row0 + 8) * ASLOT + u] = make_uint2(hA, hB);
            Al[(row0 + 8) * ASLOT + u] = make_uint2(lA, lB);
        }
        __syncthreads();

        // GEMM2: [64,128] @ [128,64] ; warp 16 x 32 (4 n-tiles)
        float acc2[4][4] = {};
#pragma unroll
        for (int s = 0; s < 8; s++) {
            uint2 u0h = Ah[ row0      * ASLOT + s * 4 + tig];
            uint2 u1h = Ah[(row0 + 8) * ASLOT + s * 4 + tig];
            uint2 u0l = Al[ row0      * ASLOT + s * 4 + tig];
            uint2 u1l = Al[(row0 + 8) * ASLOT + s * 4 + tig];
            uint32_t ah[4] = {u0h.x, u1h.x, u0h.y, u1h.y};
            uint32_t al[4] = {u0l.x, u1l.x, u0l.y, u1l.y};
#pragma unroll
            for (int nt = 0; nt < 4; nt++) {
                int bidx = (s * 4 + tig) * 68 + warpN * 32 + nt * 8 + g;
                uint2 bh = W2hU[bidx];
                uint2 bl = W2lU[bidx];
                mma_bf16(acc2[nt], ah, bh.x, bh.y);
                mma_bf16(acc2[nt], al, bh.x, bh.y);
                mma_bf16(acc2[nt], ah, bl.x, bl.y);
            }
        }
        __syncthreads();   // C1 reads done

        // epilogue2: C2 fp32 [64][65] aliases Ah region
        float* bufC = (float*)Ah;
#pragma unroll
        for (int nt = 0; nt < 4; nt++) {
            int n = warpN * 32 + nt * 8 + 2 * tig;
            float bb0 = __ldg(b2 + n), bb1 = __ldg(b2 + n + 1);
            bufC[ row0      * 65 + n    ] = fmaxf(acc2[nt][0] + bb0, 0.f);
            bufC[ row0      * 65 + n + 1] = fmaxf(acc2[nt][1] + bb1, 0.f);
            bufC[(row0 + 8) * 65 + n    ] = fmaxf(acc2[nt][2] + bb0, 0.f);
            bufC[(row0 + 8) * 65 + n + 1] = fmaxf(acc2[nt][3] + bb1, 0.f);
        }
        __syncthreads();

        // GEMM3: [64,64] @ [64,6] -> out
        for (int w = tid; w < 384; w += 256) {
            int e = w & 63, j = w >> 6;
            float s = b3s[j];
#pragma unroll 8
            for (int k = 0; k < 64; k++) s += bufC[e * 65 + k] * W3s[k * 6 + j];
            out[(ebase + e) * 6 + j] = s;
        }
        __syncthreads();   // all reads of this buffer done before restaging
        cur ^= 1;
    }
}

// ---------------------------------------------------------------------------

extern "C" void kernel_launch(void* const* d_in, const int* in_sizes, int n_in,
                              void* d_out, int out_size) {
    const float* x     = (const float*)d_in[0];
    const int*   ei    = (const int*)d_in[1];
    const float* ea    = (const float*)d_in[2];
    const float* W_enc = (const float*)d_in[3];
    const float* b_enc = (const float*)d_in[4];
    const float* W_msg = (const float*)d_in[5];
    const float* b_msg = (const float*)d_in[6];
    const float* W_upd = (const float*)d_in[7];
    const float* b_upd = (const float*)d_in[8];
    const float* W_nd1 = (const float*)d_in[9];
    const float* b_nd1 = (const float*)d_in[10];
    const float* W_nd2 = (const float*)d_in[11];
    const float* b_nd2 = (const float*)d_in[12];
    const float* W_ed1 = (const float*)d_in[13];
    const float* b_ed1 = (const float*)d_in[14];
    const float* W_ed2 = (const float*)d_in[15];
    const float* b_ed2 = (const float*)d_in[16];
    const float* W_ed3 = (const float*)d_in[17];
    const float* b_ed3 = (const float*)d_in[18];
    float* out = (float*)d_out;

    cudaFuncSetAttribute(msg_kernel, cudaFuncAttributeMaxDynamicSharedMemorySize, MSG_SMEM);
    cudaFuncSetAttribute(upd_kernel, cudaFuncAttributeMaxDynamicSharedMemorySize, UPD_SMEM);
    cudaFuncSetAttribute(edgehead_kernel, cudaFuncAttributeMaxDynamicSharedMemorySize, EH_SMEM);

    split_w_kernel<<<(SW_TOTAL + 255) / 256, 256>>>(W_msg, W_upd, W_ed1, W_ed2);
    prep_kernel<<<(EE * 4 + 255) / 256, 256>>>(ea);
    enc_kernel<<<(NN + 255) / 256, 256>>>(x, W_enc, b_enc);
    for (int l = 0; l < 3; l++) {
        msg_kernel<<<GRID_P, 256, MSG_SMEM>>>(ei, b_msg);      // launch #4 on l==0 (profiled)
        upd_kernel<<<(NN + 63) / 64, 256, UPD_SMEM>>>(b_upd);  // also zeroes g_agg
    }
    nodehead_kernel<<<(NN + 63) / 64, 256>>>(W_nd1, b_nd1, W_nd2, b_nd2, out);
    edgehead_kernel<<<GRID_P, 256, EH_SMEM>>>(ei, b_ed1, b_ed2, W_ed3, b_ed3,
                                              out + 2 * NN);
}

// round 9
// speedup vs baseline: 1.0340x; 1.0340x over previous
#include <cuda_runtime.h>
#include <cstdint>

#define NN 50000
#define EE 800000
#define IND 16
#define H 64
#define EAD 8

#define GRID_P 148

// Scratch state (no cudaMalloc allowed)
__device__ float g_h[NN * H];        // fp32 h (nodehead input)
__device__ float g_agg[NN * H];      // aggregation buffer
__device__ uint32_t g_hh2[NN * 32];  // h packed bf16x2 hi, pair-interleaved {kp,kp+4}
__device__ uint32_t g_hl2[NN * 32];  // lo
__device__ uint32_t g_eah2[EE * 8];  // ea packed hi: per edge 4 uint2 slots {pair,0}
__device__ uint32_t g_eal2[EE * 8];

// Weights, pair-format: row r = s*4+j holds uint2 {Wpair(8s+j,n), Wpair(8s+j+4,n)}
__device__ uint32_t g_Wm_h[36 * 136], g_Wm_l[36 * 136];   // msg  K=136 N=64  RS=136
__device__ uint32_t g_Wu_h[32 * 136], g_Wu_l[32 * 136];   // upd  K=128 N=64  RS=136
__device__ uint32_t g_W1_h[36 * 264], g_W1_l[36 * 264];   // ed1  K=136 N=128 RS=264
__device__ uint32_t g_W2_h[32 * 136], g_W2_l[32 * 136];   // ed2  K=128 N=64  RS=136

// ---------------------------------------------------------------------------
__device__ __forceinline__ void splitpack(float a0, float a1, uint32_t& hi, uint32_t& lo) {
    uint32_t h, l;
    asm("cvt.rn.bf16x2.f32 %0, %1, %2;" : "=r"(h) : "f"(a1), "f"(a0));
    float r0 = a0 - __uint_as_float(h << 16);
    float r1 = a1 - __uint_as_float(h & 0xFFFF0000u);
    asm("cvt.rn.bf16x2.f32 %0, %1, %2;" : "=r"(l) : "f"(r1), "f"(r0));
    hi = h; lo = l;
}

__device__ __forceinline__ void mma_bf16(float* c, const uint32_t* a, uint32_t b0, uint32_t b1) {
    asm volatile(
        "mma.sync.aligned.m16n8k16.row.col.f32.bf16.bf16.f32 "
        "{%0,%1,%2,%3}, {%4,%5,%6,%7}, {%8,%9}, {%0,%1,%2,%3};"
        : "+f"(c[0]), "+f"(c[1]), "+f"(c[2]), "+f"(c[3])
        : "r"(a[0]), "r"(a[1]), "r"(a[2]), "r"(a[3]), "r"(b0), "r"(b1));
}

#define CP_ASYNC16(saddr, gptr) \
    asm volatile("cp.async.cg.shared.global [%0], [%1], 16;" :: "r"(saddr), "l"(gptr) : "memory")
#define CP_COMMIT() asm volatile("cp.async.commit_group;" ::: "memory")
#define CP_WAIT1()  asm volatile("cp.async.wait_group 1;" ::: "memory")

__device__ __forceinline__ int hpack_idx(int p) {
    int s = p >> 3, r = p & 7;
    return (r < 4) ? (s * 4 + r) * 2 : (s * 4 + r - 4) * 2 + 1;
}

// ---------------------------------------------------------------------------
// Setup: split weights into pair-format
// ---------------------------------------------------------------------------
__device__ __forceinline__ void emit_w(const float* W, int Kp, int N, int RS,
                                       uint32_t* oh, uint32_t* ol, int i) {
    int row = i / N, n = i - row * N;
    int s = row >> 2, j = row & 3;
    int kp1 = 8 * s + j, kp2 = kp1 + 4;
    float a0 = 0.f, a1 = 0.f, c0 = 0.f, c1 = 0.f;
    if (kp1 < Kp) { a0 = W[(2 * kp1) * N + n]; a1 = W[(2 * kp1 + 1) * N + n]; }
    if (kp2 < Kp) { c0 = W[(2 * kp2) * N + n]; c1 = W[(2 * kp2 + 1) * N + n]; }
    uint32_t h1, l1, h2, l2;
    splitpack(a0, a1, h1, l1);
    splitpack(c0, c1, h2, l2);
    oh[row * RS + 2 * n] = h1; oh[row * RS + 2 * n + 1] = h2;
    ol[row * RS + 2 * n] = l1; ol[row * RS + 2 * n + 1] = l2;
}

#define SW_M (36*64)
#define SW_U (32*64)
#define SW_1 (36*128)
#define SW_2 (32*64)
#define SW_TOTAL (SW_M + SW_U + SW_1 + SW_2)

__global__ void split_w_kernel(const float* __restrict__ Wm, const float* __restrict__ Wu,
                               const float* __restrict__ W1, const float* __restrict__ W2) {
    int i = blockIdx.x * 256 + threadIdx.x;
    if (i < SW_M) { emit_w(Wm, 68, 64, 136, g_Wm_h, g_Wm_l, i); return; }
    i -= SW_M;
    if (i < SW_U) { emit_w(Wu, 64, 64, 136, g_Wu_h, g_Wu_l, i); return; }
    i -= SW_U;
    if (i < SW_1) { emit_w(W1, 68, 128, 264, g_W1_h, g_W1_l, i); return; }
    i -= SW_1;
    if (i < SW_2) { emit_w(W2, 64, 64, 136, g_W2_h, g_W2_l, i); return; }
}

// prep: split edge_attr into pair-format (+zero slot) AND zero g_agg
__global__ void prep_kernel(const float* __restrict__ ea) {
    int i = blockIdx.x * 256 + threadIdx.x;
    if (i < NN * H) g_agg[i] = 0.f;
    if (i < EE * 4) {
        int e = i >> 2, j = i & 3;
        float2 v = *(const float2*)(ea + e * EAD + 2 * j);
        uint32_t h, l;
        splitpack(v.x, v.y, h, l);
        g_eah2[e * 8 + 2 * j] = h; g_eah2[e * 8 + 2 * j + 1] = 0;
        g_eal2[e * 8 + 2 * j] = l; g_eal2[e * 8 + 2 * j + 1] = 0;
    }
}

// ---------------------------------------------------------------------------
// Encoder
// ---------------------------------------------------------------------------
__global__ void enc_kernel(const float* __restrict__ x,
                           const float* __restrict__ W,
                           const float* __restrict__ b) {
    __shared__ float Ws[IND * H];
    __shared__ float bs[H];
    for (int i = threadIdx.x; i < IND * H; i += blockDim.x) Ws[i] = W[i];
    if (threadIdx.x < H) bs[threadIdx.x] = b[threadIdx.x];
    __syncthreads();
    int node = blockIdx.x * blockDim.x + threadIdx.x;
    if (node >= NN) return;
    float xv[IND];
#pragma unroll
    for (int k = 0; k < IND; k++) xv[k] = x[node * IND + k];
#pragma unroll 4
    for (int n = 0; n < H; n += 2) {
        float a0 = bs[n], a1 = bs[n + 1];
#pragma unroll
        for (int k = 0; k < IND; k++) {
            a0 += xv[k] * Ws[k * H + n];
            a1 += xv[k] * Ws[k * H + n + 1];
        }
        g_h[node * H + n] = a0;
        g_h[node * H + n + 1] = a1;
        uint32_t h, l;
        splitpack(a0, a1, h, l);
        int idx = hpack_idx(n >> 1);
        g_hh2[node * 32 + idx] = h;
        g_hl2[node * 32 + idx] = l;
    }
}

// ---------------------------------------------------------------------------
// Staging helpers. Row = 36 uint2: slots 0..15 src-h, 16..31 dst-h, 32..35 ea.
// ---------------------------------------------------------------------------
#define ASLOT 36
#define ABUF (64 * ASLOT)        // uint2 per (hi|lo) half for 64-edge tile
#define ABUF2 (128 * ASLOT)      // ... for 128-edge tile

// 64-edge tile, 4 threads/edge (edgehead)
__device__ __forceinline__ void stage_tile(uint2* buf,
        const int* __restrict__ src, const int* __restrict__ dst,
        int tbase, int tid) {
    int e = tid >> 2, sub = tid & 3;
    int ge = tbase + e;
    int lo = sub >> 1;
    uint2* row = buf + lo * ABUF + e * ASLOT;
    uint32_t rb = (uint32_t)__cvta_generic_to_shared(row);
    const uint32_t* gh = lo ? g_hl2 : g_hh2;
    if ((sub & 1) == 0) {
        const uint32_t* p = gh + src[ge] * 32;
#pragma unroll
        for (int j = 0; j < 8; j++) CP_ASYNC16(rb + j * 16, p + j * 4);
        const uint32_t* pe = (lo ? g_eal2 : g_eah2) + ge * 8;
        CP_ASYNC16(rb + 256, pe);
        CP_ASYNC16(rb + 272, pe + 4);
    } else {
        const uint32_t* p = gh + dst[ge] * 32;
#pragma unroll
        for (int j = 0; j < 8; j++) CP_ASYNC16(rb + 128 + j * 16, p + j * 4);
    }
}

// 128-edge tile, 2 threads/edge (msg)
__device__ __forceinline__ void stage128(uint2* buf,
        const int* __restrict__ src, const int* __restrict__ dst,
        int tbase, int tid) {
    int e = tid >> 1, lo = tid & 1;
    int ge = tbase + e;
    uint2* row = buf + lo * ABUF2 + e * ASLOT;
    uint32_t rb = (uint32_t)__cvta_generic_to_shared(row);
    const uint32_t* gh = lo ? g_hl2 : g_hh2;
    const uint32_t* ps = gh + src[ge] * 32;
    const uint32_t* pd = gh + dst[ge] * 32;
#pragma unroll
    for (int j = 0; j < 8; j++) CP_ASYNC16(rb + j * 16, ps + j * 4);
#pragma unroll
    for (int j = 0; j < 8; j++) CP_ASYNC16(rb + 128 + j * 16, pd + j * 4);
    const uint32_t* pe = (lo ? g_eal2 : g_eah2) + ge * 8;
    CP_ASYNC16(rb + 256, pe);
    CP_ASYNC16(rb + 272, pe + 4);
}

// ---------------------------------------------------------------------------
// Message + scatter-add: persistent, double-buffered, tile = 128 edges,
// B in registers, dst indices prefetched one tile ahead.
// 8 warps = 4M x 2N; each warp does rows {row0, row0+8, row0+64, row0+72}.
// ---------------------------------------------------------------------------
#define NT_MSG (EE / 128)               // 6250
#define MSG_SMEM (2 * 2 * ABUF2 * 8)    // 147456 B

__global__ void __launch_bounds__(256, 1)
msg_kernel(const int* __restrict__ ei, const float* __restrict__ bias) {
    extern __shared__ uint2 smU[];
    const int* src = ei;
    const int* dst = ei + EE;
    const int tid = threadIdx.x;
    const int lane = tid & 31, warp = tid >> 5;
    const int g = lane >> 2, tig = lane & 3;
    const int warpM = warp & 3, warpN = warp >> 2;
    const int row0 = warpM * 16 + g;

    // weight panel in registers
    uint2 brh[9][4], brl[9][4];
    const uint2* WmH = (const uint2*)g_Wm_h;
    const uint2* WmL = (const uint2*)g_Wm_l;
#pragma unroll
    for (int s = 0; s < 9; s++)
#pragma unroll
        for (int nt = 0; nt < 4; nt++) {
            int idx = (s * 4 + tig) * 68 + warpN * 32 + nt * 8 + g;
            brh[s][nt] = WmH[idx];
            brl[s][nt] = WmL[idx];
        }
    float2 bv[4];
#pragma unroll
    for (int nt = 0; nt < 4; nt++) {
        int n = warpN * 32 + nt * 8 + 2 * tig;
        bv[nt] = make_float2(__ldg(bias + n), __ldg(bias + n + 1));
    }

    int t = blockIdx.x, cur = 0;
    int d[4];
    if (t < NT_MSG) {
        stage128(smU, src, dst, t * 128, tid);
        const int tb = t * 128;
        d[0] = dst[tb + row0];      d[1] = dst[tb + row0 + 8];
        d[2] = dst[tb + row0 + 64]; d[3] = dst[tb + row0 + 72];
    }
    CP_COMMIT();

    for (; t < NT_MSG; t += GRID_P) {
        int tn = t + GRID_P;
        int dn[4];
        if (tn < NT_MSG) {
            stage128(smU + (cur ^ 1) * 2 * ABUF2, src, dst, tn * 128, tid);
            const int tb = tn * 128;
            dn[0] = dst[tb + row0];      dn[1] = dst[tb + row0 + 8];
            dn[2] = dst[tb + row0 + 64]; dn[3] = dst[tb + row0 + 72];
        }
        CP_COMMIT();
        CP_WAIT1();
        __syncthreads();

        const uint2* Ah = smU + cur * 2 * ABUF2;
        const uint2* Al = Ah + ABUF2;
        float acc[2][4][4] = {};
#pragma unroll
        for (int s = 0; s < 9; s++) {
#pragma unroll
            for (int blk = 0; blk < 2; blk++) {
                int r = row0 + blk * 64;
                uint2 u0h = Ah[ r      * ASLOT + s * 4 + tig];
                uint2 u1h = Ah[(r + 8) * ASLOT + s * 4 + tig];
                uint2 u0l = Al[ r      * ASLOT + s * 4 + tig];
                uint2 u1l = Al[(r + 8) * ASLOT + s * 4 + tig];
                uint32_t ah[4] = {u0h.x, u1h.x, u0h.y, u1h.y};
                uint32_t al[4] = {u0l.x, u1l.x, u0l.y, u1l.y};
#pragma unroll
                for (int nt = 0; nt < 4; nt++) {
                    mma_bf16(acc[blk][nt], ah, brh[s][nt].x, brh[s][nt].y);
                    mma_bf16(acc[blk][nt], al, brh[s][nt].x, brh[s][nt].y);
                    mma_bf16(acc[blk][nt], ah, brl[s][nt].x, brl[s][nt].y);
                }
            }
        }

#pragma unroll
        for (int blk = 0; blk < 2; blk++) {
            const int d0 = d[blk * 2], d1 = d[blk * 2 + 1];
#pragma unroll
            for (int nt = 0; nt < 4; nt++) {
                int n = warpN * 32 + nt * 8 + 2 * tig;
                atomicAdd((float2*)(g_agg + d0 * H + n),
                          make_float2(fmaxf(acc[blk][nt][0] + bv[nt].x, 0.f),
                                      fmaxf(acc[blk][nt][1] + bv[nt].y, 0.f)));
                atomicAdd((float2*)(g_agg + d1 * H + n),
                          make_float2(fmaxf(acc[blk][nt][2] + bv[nt].x, 0.f),
                                      fmaxf(acc[blk][nt][3] + bv[nt].y, 0.f)));
            }
        }
        d[0] = dn[0]; d[1] = dn[1]; d[2] = dn[2]; d[3] = dn[3];
        __syncthreads();
        cur ^= 1;
    }
}

// ---------------------------------------------------------------------------
// Update: h = relu([h | agg] @ W_upd + b), zeroes g_agg as it reads it.
// ---------------------------------------------------------------------------
#define UPD_SMEM (2 * 64 * ASLOT * 8)   // 36864 B

__global__ void __launch_bounds__(256, 1)
upd_kernel(const float* __restrict__ bias) {
    extern __shared__ uint2 smU[];
    uint2* Ah = smU;
    uint2* Al = smU + 64 * ASLOT;
    const int nbase = blockIdx.x * 64;
    const int tid = threadIdx.x;
    const int lane = tid & 31, warp = tid >> 5;
    const int g = lane >> 2, tig = lane & 3;
    const int warpM = warp & 3, warpN = warp >> 2;
    const int row0 = warpM * 16 + g;

    uint2 brh[8][4], brl[8][4];
    const uint2* WuH = (const uint2*)g_Wu_h;
    const uint2* WuL = (const uint2*)g_Wu_l;
#pragma unroll
    for (int s = 0; s < 8; s++)
#pragma unroll
        for (int nt = 0; nt < 4; nt++) {
            int idx = (s * 4 + tig) * 68 + warpN * 32 + nt * 8 + g;
            brh[s][nt] = WuH[idx];
            brl[s][nt] = WuL[idx];
        }

    for (int i = tid; i < 64 * 32; i += 256) {
        int nd = i >> 5, u = i & 31;
        int gn = nbase + nd;
        if (u < 16) {
            uint2 h = make_uint2(0, 0), l = make_uint2(0, 0);
            if (gn < NN) {
                h = ((const uint2*)g_hh2)[gn * 16 + u];
                l = ((const uint2*)g_hl2)[gn * 16 + u];
            }
            Ah[nd * ASLOT + u] = h;
            Al[nd * ASLOT + u] = l;
        } else {
            int s = u >> 2, j = u & 3;
            int pa1 = 8 * (s - 4) + j, pa2 = pa1 + 4;
            uint32_t h1 = 0, l1 = 0, h2 = 0, l2 = 0;
            if (gn < NN) {
                float2 v1 = *(float2*)(g_agg + gn * H + 2 * pa1);
                float2 v2 = *(float2*)(g_agg + gn * H + 2 * pa2);
                splitpack(v1.x, v1.y, h1, l1);
                splitpack(v2.x, v2.y, h2, l2);
                *(float2*)(g_agg + gn * H + 2 * pa1) = make_float2(0.f, 0.f);
                *(float2*)(g_agg + gn * H + 2 * pa2) = make_float2(0.f, 0.f);
            }
            Ah[nd * ASLOT + u] = make_uint2(h1, h2);
            Al[nd * ASLOT + u] = make_uint2(l1, l2);
        }
    }
    __syncthreads();

    float acc[4][4] = {};
#pragma unroll
    for (int s = 0; s < 8; s++) {
        uint2 u0h = Ah[ row0      * ASLOT + s * 4 + tig];
        uint2 u1h = Ah[(row0 + 8) * ASLOT + s * 4 + tig];
        uint2 u0l = Al[ row0      * ASLOT + s * 4 + tig];
        uint2 u1l = Al[(row0 + 8) * ASLOT + s * 4 + tig];
        uint32_t ah[4] = {u0h.x, u1h.x, u0h.y, u1h.y};
        uint32_t al[4] = {u0l.x, u1l.x, u0l.y, u1l.y};
#pragma unroll
        for (int nt = 0; nt < 4; nt++) {
            mma_bf16(acc[nt], ah, brh[s][nt].x, brh[s][nt].y);
            mma_bf16(acc[nt], al, brh[s][nt].x, brh[s][nt].y);
            mma_bf16(acc[nt], ah, brl[s][nt].x, brl[s][nt].y);
        }
    }

    const int gn0 = nbase + row0, gn1 = nbase + row0 + 8;
#pragma unroll
    for (int nt = 0; nt < 4; nt++) {
        int n = warpN * 32 + nt * 8 + 2 * tig;
        int p = n >> 1;
        int idx = hpack_idx(p);
        float bb0 = __ldg(bias + n), bb1 = __ldg(bias + n + 1);
        if (gn0 < NN) {
            float v0 = fmaxf(acc[nt][0] + bb0, 0.f);
            float v1 = fmaxf(acc[nt][1] + bb1, 0.f);
            *(float2*)(g_h + gn0 * H + n) = make_float2(v0, v1);
            splitpack(v0, v1, g_hh2[gn0 * 32 + idx], g_hl2[gn0 * 32 + idx]);
        }
        if (gn1 < NN) {
            float v0 = fmaxf(acc[nt][2] + bb0, 0.f);
            float v1 = fmaxf(acc[nt][3] + bb1, 0.f);
            *(float2*)(g_h + gn1 * H + n) = make_float2(v0, v1);
            splitpack(v0, v1, g_hh2[gn1 * 32 + idx], g_hl2[gn1 * 32 + idx]);
        }
    }
}

// ---------------------------------------------------------------------------
// Node head (FFMA)
// ---------------------------------------------------------------------------
__global__ void __launch_bounds__(256)
nodehead_kernel(const float* __restrict__ W1, const float* __restrict__ b1,
                const float* __restrict__ W2, const float* __restrict__ b2,
                float* __restrict__ out) {
    __shared__ float As[64 * 64];
    __shared__ float Ws[64 * 64];
    __shared__ float W2s[64 * 2];
    __shared__ float b2s[2];
    int nbase = blockIdx.x * 64;

    for (int i = threadIdx.x; i < 64 * 64; i += 256) Ws[i] = W1[i];
    if (threadIdx.x < 128) W2s[threadIdx.x] = W2[threadIdx.x];
    if (threadIdx.x < 2) b2s[threadIdx.x] = b2[threadIdx.x];
    for (int i = threadIdx.x; i < 64 * 64; i += 256) {
        int nd = i >> 6, k = i & 63;
        int gn = nbase + nd;
        As[i] = (gn < NN) ? g_h[gn * H + k] : 0.f;
    }
    __syncthreads();

    int tn = threadIdx.x & 15, te = threadIdx.x >> 4;
    float acc[4][4] = {};
    for (int k = 0; k < 64; k += 4) {
        float4 av4[4];
#pragma unroll
        for (int i = 0; i < 4; i++)
            av4[i] = *(const float4*)(As + (te * 4 + i) * 64 + k);
        const float* av = (const float*)av4;
#pragma unroll
        for (int kk = 0; kk < 4; kk++) {
            float4 w = *(const float4*)(Ws + (k + kk) * H + tn * 4);
#pragma unroll
            for (int i = 0; i < 4; i++) {
                float a = av[i * 4 + kk];
                acc[i][0] += a * w.x;
                acc[i][1] += a * w.y;
                acc[i][2] += a * w.z;
                acc[i][3] += a * w.w;
            }
        }
    }
    __syncthreads();

    float4 bvv = *(const float4*)(b1 + tn * 4);
    const float* bvp = (const float*)&bvv;
#pragma unroll
    for (int i = 0; i < 4; i++)
#pragma unroll
        for (int j = 0; j < 4; j++)
            As[(tn * 4 + j) * 64 + te * 4 + i] = fmaxf(acc[i][j] + bvp[j], 0.f);
    __syncthreads();

    if (threadIdx.x < 128) {
        int nd = threadIdx.x & 63, j = threadIdx.x >> 6;
        int gn = nbase + nd;
        if (gn < NN) {
            float s = b2s[j];
#pragma unroll 8
            for (int k = 0; k < 64; k++) s += As[k * 64 + nd] * W2s[k * 2 + j];
            out[gn * 2 + j] = s;
        }
    }
}

// ---------------------------------------------------------------------------
// Edge head: persistent, weights resident (pair-format), double-buffered.
// ---------------------------------------------------------------------------
#define NT_EH (EE / 64)
#define EH_SMEM (4*ABUF*8 + 2*9504*4 + 2*4352*4 + 390*4)   // 186136 B

__global__ void __launch_bounds__(256, 1)
edgehead_kernel(const int* __restrict__ ei,
                const float* __restrict__ b1, const float* __restrict__ b2,
                const float* __restrict__ W3, const float* __restrict__ b3,
                float* __restrict__ out) {
    extern __shared__ uint2 smU[];
    uint32_t* W1h = (uint32_t*)(smU + 4 * ABUF);
    uint32_t* W1l = W1h + 9504;
    uint32_t* W2h = W1l + 9504;
    uint32_t* W2l = W2h + 4352;
    float*    W3s = (float*)(W2l + 4352);
    float*    b3s = W3s + 384;
    const int* src = ei;
    const int* dst = ei + EE;
    const int tid = threadIdx.x;

    for (int i = tid; i < 9504; i += 256) { W1h[i] = g_W1_h[i]; W1l[i] = g_W1_l[i]; }
    for (int i = tid; i < 4352; i += 256) { W2h[i] = g_W2_h[i]; W2l[i] = g_W2_l[i]; }
    for (int i = tid; i < 384; i += 256) W3s[i] = W3[i];
    if (tid < 6) b3s[tid] = b3[tid];

    const int lane = tid & 31, warp = tid >> 5;
    const int g = lane >> 2, tig = lane & 3;
    const int warpM = warp & 3, warpN = warp >> 2;
    const int row0 = warpM * 16 + g;
    __syncthreads();

    const uint2* W1hU = (const uint2*)W1h;
    const uint2* W1lU = (const uint2*)W1l;
    const uint2* W2hU = (const uint2*)W2h;
    const uint2* W2lU = (const uint2*)W2l;

    int t = blockIdx.x, cur = 0;
    if (t < NT_EH) stage_tile(smU, src, dst, t * 64, tid);
    CP_COMMIT();

    for (; t < NT_EH; t += GRID_P) {
        int tn = t + GRID_P;
        if (tn < NT_EH) stage_tile(smU + (cur ^ 1) * 2 * ABUF, src, dst, tn * 64, tid);
        CP_COMMIT();
        CP_WAIT1();
        __syncthreads();

        uint2* Ah = smU + cur * 2 * ABUF;
        uint2* Al = Ah + ABUF;
        const int ebase = t * 64;

        // GEMM1: [64,136] @ [136,128]
        float acc1[8][4] = {};
#pragma unroll
        for (int s = 0; s < 9; s++) {
            uint2 u0h = Ah[ row0      * ASLOT + s * 4 + tig];
            uint2 u1h = Ah[(row0 + 8) * ASLOT + s * 4 + tig];
            uint2 u0l = Al[ row0      * ASLOT + s * 4 + tig];
            uint2 u1l = Al[(row0 + 8) * ASLOT + s * 4 + tig];
            uint32_t ah[4] = {u0h.x, u1h.x, u0h.y, u1h.y};
            uint32_t al[4] = {u0l.x, u1l.x, u0l.y, u1l.y};
#pragma unroll
            for (int nt = 0; nt < 8; nt++) {
                int bidx = (s * 4 + tig) * 132 + warpN * 64 + nt * 8 + g;
                uint2 bh = W1hU[bidx];
                uint2 bl = W1lU[bidx];
                mma_bf16(acc1[nt], ah, bh.x, bh.y);
                mma_bf16(acc1[nt], al, bh.x, bh.y);
                mma_bf16(acc1[nt], ah, bl.x, bl.y);
            }
        }
        __syncthreads();

        // epilogue1 -> pair-interleaved C1 in Ah/Al
#pragma unroll
        for (int nt = 0; nt < 8; nt += 2) {
            int n0 = warpN * 64 + nt * 8 + 2 * tig;
            int n1 = n0 + 8;
            float b00 = __ldg(b1 + n0), b01 = __ldg(b1 + n0 + 1);
            float b10 = __ldg(b1 + n1), b11 = __ldg(b1 + n1 + 1);
            int u = (warpN * 4 + (nt >> 1)) * 4 + tig;
            uint32_t hA, lA, hB, lB;
            splitpack(fmaxf(acc1[nt][0] + b00, 0.f), fmaxf(acc1[nt][1] + b01, 0.f), hA, lA);
            splitpack(fmaxf(acc1[nt + 1][0] + b10, 0.f), fmaxf(acc1[nt + 1][1] + b11, 0.f), hB, lB);
            Ah[row0 * ASLOT + u] = make_uint2(hA, hB);
            Al[row0 * ASLOT + u] = make_uint2(lA, lB);
            splitpack(fmaxf(acc1[nt][2] + b00, 0.f), fmaxf(acc1[nt][3] + b01, 0.f), hA, lA);
            splitpack(fmaxf(acc1[nt + 1][2] + b10, 0.f), fmaxf(acc1[nt + 1][3] + b11, 0.f), hB, lB);
            Ah[(row0 + 8) * ASLOT + u] = make_uint2(hA, hB);
            Al[(row0 + 8) * ASLOT + u] = make_uint2(lA, lB);
        }
        __syncthreads();

        // GEMM2: [64,128] @ [128,64]
        float acc2[4][4] = {};
#pragma unroll
        for (int s = 0; s < 8; s++) {
            uint2 u0h = Ah[ row0      * ASLOT + s * 4 + tig];
            uint2 u1h = Ah[(row0 + 8) * ASLOT + s * 4 + tig];
            uint2 u0l = Al[ row0      * ASLOT + s * 4 + tig];
            uint2 u1l = Al[(row0 + 8) * ASLOT + s * 4 + tig];
            uint32_t ah[4] = {u0h.x, u1h.x, u0h.y, u1h.y};
            uint32_t al[4] = {u0l.x, u1l.x, u0l.y, u1l.y};
#pragma unroll
            for (int nt = 0; nt < 4; nt++) {
                int bidx = (s * 4 + tig) * 68 + warpN * 32 + nt * 8 + g;
                uint2 bh = W2hU[bidx];
                uint2 bl = W2lU[bidx];
                mma_bf16(acc2[nt], ah, bh.x, bh.y);
                mma_bf16(acc2[nt], al, bh.x, bh.y);
                mma_bf16(acc2[nt], ah, bl.x, bl.y);
            }
        }
        __syncthreads();

        // epilogue2: C2 fp32 [64][65] aliases Ah region
        float* bufC = (float*)Ah;
#pragma unroll
        for (int nt = 0; nt < 4; nt++) {
            int n = warpN * 32 + nt * 8 + 2 * tig;
            float bb0 = __ldg(b2 + n), bb1 = __ldg(b2 + n + 1);
            bufC[ row0      * 65 + n    ] = fmaxf(acc2[nt][0] + bb0, 0.f);
            bufC[ row0      * 65 + n + 1] = fmaxf(acc2[nt][1] + bb1, 0.f);
            bufC[(row0 + 8) * 65 + n    ] = fmaxf(acc2[nt][2] + bb0, 0.f);
            bufC[(row0 + 8) * 65 + n + 1] = fmaxf(acc2[nt][3] + bb1, 0.f);
        }
        __syncthreads();

        // GEMM3
        for (int w = tid; w < 384; w += 256) {
            int e = w & 63, j = w >> 6;
            float s = b3s[j];
#pragma unroll 8
            for (int k = 0; k < 64; k++) s += bufC[e * 65 + k] * W3s[k * 6 + j];
            out[(ebase + e) * 6 + j] = s;
        }
        __syncthreads();
        cur ^= 1;
    }
}

// ---------------------------------------------------------------------------

extern "C" void kernel_launch(void* const* d_in, const int* in_sizes, int n_in,
                              void* d_out, int out_size) {
    const float* x     = (const float*)d_in[0];
    const int*   ei    = (const int*)d_in[1];
    const float* ea    = (const float*)d_in[2];
    const float* W_enc = (const float*)d_in[3];
    const float* b_enc = (const float*)d_in[4];
    const float* W_msg = (const float*)d_in[5];
    const float* b_msg = (const float*)d_in[6];
    const float* W_upd = (const float*)d_in[7];
    const float* b_upd = (const float*)d_in[8];
    const float* W_nd1 = (const float*)d_in[9];
    const float* b_nd1 = (const float*)d_in[10];
    const float* W_nd2 = (const float*)d_in[11];
    const float* b_nd2 = (const float*)d_in[12];
    const float* W_ed1 = (const float*)d_in[13];
    const float* b_ed1 = (const float*)d_in[14];
    const float* W_ed2 = (const float*)d_in[15];
    const float* b_ed2 = (const float*)d_in[16];
    const float* W_ed3 = (const float*)d_in[17];
    const float* b_ed3 = (const float*)d_in[18];
    float* out = (float*)d_out;

    cudaFuncSetAttribute(msg_kernel, cudaFuncAttributeMaxDynamicSharedMemorySize, MSG_SMEM);
    cudaFuncSetAttribute(upd_kernel, cudaFuncAttributeMaxDynamicSharedMemorySize, UPD_SMEM);
    cudaFuncSetAttribute(edgehead_kernel, cudaFuncAttributeMaxDynamicSharedMemorySize, EH_SMEM);

    split_w_kernel<<<(SW_TOTAL + 255) / 256, 256>>>(W_msg, W_upd, W_ed1, W_ed2);
    prep_kernel<<<(EE * 4 + 255) / 256, 256>>>(ea);
    enc_kernel<<<(NN + 255) / 256, 256>>>(x, W_enc, b_enc);
    for (int l = 0; l < 3; l++) {
        msg_kernel<<<GRID_P, 256, MSG_SMEM>>>(ei, b_msg);      // launch #4 on l==0 (profiled)
        upd_kernel<<<(NN + 63) / 64, 256, UPD_SMEM>>>(b_upd);
    }
    nodehead_kernel<<<(NN + 63) / 64, 256>>>(W_nd1, b_nd1, W_nd2, b_nd2, out);
    edgehead_kernel<<<GRID_P, 256, EH_SMEM>>>(ei, b_ed1, b_ed2, W_ed3, b_ed3,
                                              out + 2 * NN);
}